// round 10
// baseline (speedup 1.0000x reference)
#include <cuda_runtime.h>

// ---------------------------------------------------------------------------
// SWMSA: shifted-window multi-head self-attention (Swin block attention)
// B=32, H=W=56, WS=7, SS=3, NH=8, E=256, HD=32, NW=64, WD=49
// Kernel A: one-shot rel-pos-bias expansion
// Kernel B: tensor-core fused QKV + attention; block = (window, 2 heads),
//           4 warps/head, 1 m-tile/warp, 62.9KB smem -> 3 blocks/SM
// Kernel C: output projection GEMM [TF32 MMA]
// ---------------------------------------------------------------------------

#define BNUM 32
#define HW   56
#define NHEAD 8
#define EMB  256
#define HDIM 32
#define NWIN 64
#define WD   49
#define NTOK (HW*HW)              // 3136

__device__ __align__(16) float g_O [(size_t)BNUM*NTOK*EMB];
__device__ __align__(16) float g_Bi[NHEAD*WD*WD];     // 19208 floats

// ---------------------------------------------------------------------------
__global__ __launch_bounds__(512) void bias_kernel(const float* __restrict__ rpb) {
    int i = blockIdx.x * 512 + threadIdx.x;
    if (i >= NHEAD*WD*WD) return;
    int h  = i / (WD*WD);
    int r2 = i - h*(WD*WD);
    int a  = r2 / WD;
    int bb = r2 - a*WD;
    int idx = (a/7 - bb/7 + 6)*13 + (a%7 - bb%7 + 6);
    g_Bi[i] = rpb[idx*NHEAD + h];
}

// ---------------------------------------------------------------------------
__device__ __forceinline__ unsigned f2tf32(float f) {
    unsigned r;
    asm("cvt.rna.tf32.f32 %0, %1;" : "=r"(r) : "f"(f));
    return r;
}

__device__ __forceinline__ void mma_tf32(float* c, unsigned a0, unsigned a1,
                                         unsigned a2, unsigned a3,
                                         unsigned b0, unsigned b1) {
    asm volatile(
        "mma.sync.aligned.m16n8k8.row.col.f32.tf32.tf32.f32 "
        "{%0,%1,%2,%3}, {%4,%5,%6,%7}, {%8,%9}, {%0,%1,%2,%3};\n"
        : "+f"(c[0]), "+f"(c[1]), "+f"(c[2]), "+f"(c[3])
        : "r"(a0), "r"(a1), "r"(a2), "r"(a3), "r"(b0), "r"(b1));
}

// ---------------------------------------------------------------------------
// Fused kernel smem layout (floats), block = (window, 2 heads):
//   Ks  @ 0     : 2 heads x 32 d x 56 j (tf32)            = 3584
//   Vs  @ 3584  : 2 heads x 32 d x 60 j (tf32, zeroed)    = 3840
//   Ws  @ 7424  : 32 k x stride 104 (tf32)                = 3328
//   Bis @ 10752 : 2 heads x 49x49 bias+mask (fp32)        = 4802
//   bs  @ 15554 : 96 (fp32)
//   gof @ 15650 : 64 ints (token -> global element offset)
//   total 15714 floats = 62,856 B -> 3 blocks/SM (256 thr, <=85 regs)
// ---------------------------------------------------------------------------
#define OFF_KS 0
#define KS_H   1792      // 32*56
#define OFF_VS 3584
#define VS_H   1920      // 32*60
#define OFF_WS 7424
#define WS_S   104
#define OFF_BI 10752
#define OFF_BS 15554
#define OFF_GO 15650
#define SMEM_FLOATS 15714

__global__ __launch_bounds__(256, 3) void fused_kernel(const float* __restrict__ x,
                                                       const float* __restrict__ Wq,
                                                       const float* __restrict__ bq) {
    extern __shared__ float sm[];
    float* bs  = sm + OFF_BS;
    float* Bis = sm + OFF_BI;
    int*   gof = reinterpret_cast<int*>(sm + OFF_GO);
    unsigned* Wsu = reinterpret_cast<unsigned*>(sm + OFF_WS);

    int bid = blockIdx.x;
    int hg = bid & 3, bw = bid >> 2;
    int b  = bw >> 6, w = bw & 63;
    int wr = w >> 3,  wc = w & 7;
    int tid = threadIdx.x, warp = tid >> 5, lane = tid & 31;
    int g = lane >> 2, t = lane & 3;
    int lh = warp >> 2, p = warp & 3;          // local head (0/1), warp-in-head
    int h = hg*2 + lh;
    int m0 = p*16 - (p == 3 ? 15 : 0);         // m-tile base: 0,16,32,33

    // zero Vs (j-pad columns must be exact 0 for PV)
    {
        float4* z = reinterpret_cast<float4*>(sm + OFF_VS);
        for (int i = tid; i < 3840/4; i += 256) z[i] = make_float4(0,0,0,0);
    }
    // stage qkv weights (tf32) + bias (fp32)
    for (int i = tid; i < 32*96; i += 256) {
        int k = i / 96, n = i - k*96;
        Wsu[k*WS_S + n] = f2tf32(Wq[i]);
    }
    if (tid < 96) bs[tid] = bq[tid];
    if (tid < WD) {
        int tr = tid/7, tc = tid - 7*tr;
        int row = wr*7 + tr + 3; if (row >= HW) row -= HW;
        int col = wc*7 + tc + 3; if (col >= HW) col -= HW;
        gof[tid] = (b*NTOK + row*HW + col)*EMB;
    }
    // stage rel-pos bias + shift mask, combined, for this block's 2 heads
    for (int e = tid; e < WD*WD; e += 256) {
        int i = e / WD, j = e - WD*i;
        int itr = i/7, itc = i - 7*itr;
        int jtr = j/7, jtc = j - 7*jtr;
        int irs = wr*7 + itr, ics = wc*7 + itc;
        int jrs = wr*7 + jtr, jcs = wc*7 + jtc;
        int ri = ((irs<49)?0:((irs<53)?1:2))*3 + ((ics<49)?0:((ics<53)?1:2));
        int rj = ((jrs<49)?0:((jrs<53)?1:2))*3 + ((jcs<49)?0:((jcs<53)?1:2));
        float msk = (ri == rj) ? 0.f : -100.f;
        Bis[e]         = g_Bi[(hg*2  )*(WD*WD) + e] + msk;
        Bis[WD*WD + e] = g_Bi[(hg*2+1)*(WD*WD) + e] + msk;
    }
    __syncthreads();

    // ---- A-frags (x rows, this head's 32-col slice) direct from global ----
    int hc = h*HDIM;
    int r0 = gof[m0+g]   + hc;
    int r1 = gof[m0+g+8] + hc;
    unsigned a_[4][4];
#pragma unroll
    for (int ks = 0; ks < 4; ++ks) {
        int k0 = ks*8;
        a_[ks][0] = f2tf32(__ldg(x + r0 + k0 + t    ));
        a_[ks][1] = f2tf32(__ldg(x + r1 + k0 + t    ));
        a_[ks][2] = f2tf32(__ldg(x + r0 + k0 + t + 4));
        a_[ks][3] = f2tf32(__ldg(x + r1 + k0 + t + 4));
    }

    // ---- Q pass (cols 0..31) -> c-frags (scaled, tf32) ----
    unsigned qu[4][4];
    const float qscale = 0.17677669529663687f;
#pragma unroll
    for (int nt = 0; nt < 4; ++nt) {
        float c4[4] = {0.f,0.f,0.f,0.f};
#pragma unroll
        for (int ks = 0; ks < 4; ++ks) {
            int k0 = ks*8;
            unsigned b0 = Wsu[(k0+t  )*WS_S + nt*8 + g];
            unsigned b1 = Wsu[(k0+t+4)*WS_S + nt*8 + g];
            mma_tf32(c4, a_[ks][0],a_[ks][1],a_[ks][2],a_[ks][3], b0,b1);
        }
        int d0 = nt*8 + 2*t;
        qu[nt][0] = f2tf32((c4[0] + bs[d0  ]) * qscale);
        qu[nt][1] = f2tf32((c4[1] + bs[d0+1]) * qscale);
        qu[nt][2] = f2tf32((c4[2] + bs[d0  ]) * qscale);
        qu[nt][3] = f2tf32((c4[3] + bs[d0+1]) * qscale);
    }
    // ---- K pass (cols 32..63) -> Ks[d][j] stride 56 ----
    {
        unsigned* Kh = reinterpret_cast<unsigned*>(sm + OFF_KS) + lh*KS_H;
#pragma unroll
        for (int nt = 0; nt < 4; ++nt) {
            float c4[4] = {0.f,0.f,0.f,0.f};
#pragma unroll
            for (int ks = 0; ks < 4; ++ks) {
                int k0 = ks*8;
                unsigned b0 = Wsu[(k0+t  )*WS_S + 32 + nt*8 + g];
                unsigned b1 = Wsu[(k0+t+4)*WS_S + 32 + nt*8 + g];
                mma_tf32(c4, a_[ks][0],a_[ks][1],a_[ks][2],a_[ks][3], b0,b1);
            }
            int d0 = nt*8 + 2*t;
            Kh[(d0  )*56 + m0+g  ] = f2tf32(c4[0] + bs[32+d0  ]);
            Kh[(d0+1)*56 + m0+g  ] = f2tf32(c4[1] + bs[32+d0+1]);
            Kh[(d0  )*56 + m0+g+8] = f2tf32(c4[2] + bs[32+d0  ]);
            Kh[(d0+1)*56 + m0+g+8] = f2tf32(c4[3] + bs[32+d0+1]);
        }
    }
    // ---- V pass (cols 64..95) -> Vs[d][j] stride 60 (transposed) ----
    {
        unsigned* Vh = reinterpret_cast<unsigned*>(sm + OFF_VS) + lh*VS_H;
#pragma unroll
        for (int nt = 0; nt < 4; ++nt) {
            float c4[4] = {0.f,0.f,0.f,0.f};
#pragma unroll
            for (int ks = 0; ks < 4; ++ks) {
                int k0 = ks*8;
                unsigned b0 = Wsu[(k0+t  )*WS_S + 64 + nt*8 + g];
                unsigned b1 = Wsu[(k0+t+4)*WS_S + 64 + nt*8 + g];
                mma_tf32(c4, a_[ks][0],a_[ks][1],a_[ks][2],a_[ks][3], b0,b1);
            }
            int d0 = nt*8 + 2*t;
            Vh[(d0  )*60 + m0+g  ] = f2tf32(c4[0] + bs[64+d0  ]);
            Vh[(d0+1)*60 + m0+g  ] = f2tf32(c4[1] + bs[64+d0+1]);
            Vh[(d0  )*60 + m0+g+8] = f2tf32(c4[2] + bs[64+d0  ]);
            Vh[(d0+1)*60 + m0+g+8] = f2tf32(c4[3] + bs[64+d0+1]);
        }
    }

    // rearrange Q c-frags -> a-frags via warp shuffles (warp-local, pre-sync ok)
    int src0 = (g << 2) | (t >> 1);
    unsigned qa[4][4];
#pragma unroll
    for (int ks = 0; ks < 4; ++ks) {
        unsigned v00 = __shfl_sync(0xffffffffu, qu[ks][0], src0);
        unsigned v01 = __shfl_sync(0xffffffffu, qu[ks][1], src0);
        unsigned v02 = __shfl_sync(0xffffffffu, qu[ks][2], src0);
        unsigned v03 = __shfl_sync(0xffffffffu, qu[ks][3], src0);
        unsigned v10 = __shfl_sync(0xffffffffu, qu[ks][0], src0+2);
        unsigned v11 = __shfl_sync(0xffffffffu, qu[ks][1], src0+2);
        unsigned v12 = __shfl_sync(0xffffffffu, qu[ks][2], src0+2);
        unsigned v13 = __shfl_sync(0xffffffffu, qu[ks][3], src0+2);
        bool odd = (t & 1);
        qa[ks][0] = odd ? v01 : v00;
        qa[ks][1] = odd ? v03 : v02;
        qa[ks][2] = odd ? v11 : v10;
        qa[ks][3] = odd ? v13 : v12;
    }

    __syncthreads();   // K/V from all 4 warps of each head visible

    // ---- scores: S = Q · K^T ----
    float s[7][4];
#pragma unroll
    for (int nt = 0; nt < 7; ++nt)
        s[nt][0]=s[nt][1]=s[nt][2]=s[nt][3]=0.f;
    {
        const unsigned* Kh = reinterpret_cast<const unsigned*>(sm + OFF_KS) + lh*KS_H;
#pragma unroll
        for (int ks = 0; ks < 4; ++ks) {
            int k0 = ks*8;
#pragma unroll
            for (int nt = 0; nt < 7; ++nt) {
                unsigned b0 = Kh[(k0+t  )*56 + nt*8 + g];
                unsigned b1 = Kh[(k0+t+4)*56 + nt*8 + g];
                mma_tf32(s[nt], qa[0][0]?qa[ks][0]:qa[ks][0], qa[ks][1],qa[ks][2],qa[ks][3], b0,b1);
            }
        }
    }

    // ---- softmax (single pass; bias+mask pre-combined in smem) ----
    float inv_l[2];
    const float* Bh = Bis + lh*(WD*WD);
#pragma unroll
    for (int half = 0; half < 2; ++half) {
        int i = m0 + g + half*8;
        const float* Br = Bh + i*WD;
        float mx = -1e30f;
#pragma unroll
        for (int nt = 0; nt < 7; ++nt) {
#pragma unroll
            for (int c = 0; c < 2; ++c) {
                int j = nt*8 + 2*t + c;
                float v = (j < WD) ? s[nt][half*2+c] + Br[j] : -1e30f;
                s[nt][half*2+c] = v;
                mx = fmaxf(mx, v);
            }
        }
        mx = fmaxf(mx, __shfl_xor_sync(0xffffffffu, mx, 1));
        mx = fmaxf(mx, __shfl_xor_sync(0xffffffffu, mx, 2));
        float l = 0.f;
#pragma unroll
        for (int nt = 0; nt < 7; ++nt)
#pragma unroll
            for (int c = 0; c < 2; ++c) {
                float e = __expf(s[nt][half*2+c] - mx);
                s[nt][half*2+c] = e;
                l += e;
            }
        l += __shfl_xor_sync(0xffffffffu, l, 1);
        l += __shfl_xor_sync(0xffffffffu, l, 2);
        inv_l[half] = 1.f / l;
    }
    // convert P to tf32 bits in place
#pragma unroll
    for (int nt = 0; nt < 7; ++nt)
#pragma unroll
        for (int c = 0; c < 4; ++c)
            s[nt][c] = __uint_as_float(f2tf32(s[nt][c]));

    // ---- PV: O = P · V  (V stored [d][j]: B[k=j][n=d] = Vh[n*60 + k]) ----
    float o[4][4];
#pragma unroll
    for (int nt = 0; nt < 4; ++nt)
        o[nt][0]=o[nt][1]=o[nt][2]=o[nt][3]=0.f;
    {
        const unsigned* Vh = reinterpret_cast<const unsigned*>(sm + OFF_VS) + lh*VS_H;
#pragma unroll
        for (int ks = 0; ks < 7; ++ks) {
            int k0 = ks*8;
            float v00 = __shfl_sync(0xffffffffu, s[ks][0], src0);
            float v01 = __shfl_sync(0xffffffffu, s[ks][1], src0);
            float v02 = __shfl_sync(0xffffffffu, s[ks][2], src0);
            float v03 = __shfl_sync(0xffffffffu, s[ks][3], src0);
            float v10 = __shfl_sync(0xffffffffu, s[ks][0], src0+2);
            float v11 = __shfl_sync(0xffffffffu, s[ks][1], src0+2);
            float v12 = __shfl_sync(0xffffffffu, s[ks][2], src0+2);
            float v13 = __shfl_sync(0xffffffffu, s[ks][3], src0+2);
            bool odd = (t & 1);
            unsigned pa0 = __float_as_uint(odd ? v01 : v00);
            unsigned pa1 = __float_as_uint(odd ? v03 : v02);
            unsigned pa2 = __float_as_uint(odd ? v11 : v10);
            unsigned pa3 = __float_as_uint(odd ? v13 : v12);
#pragma unroll
            for (int nt = 0; nt < 4; ++nt) {
                unsigned b0 = Vh[(nt*8+g)*60 + k0+t  ];
                unsigned b1 = Vh[(nt*8+g)*60 + k0+t+4];
                mma_tf32(o[nt], pa0,pa1,pa2,pa3, b0,b1);
            }
        }
    }

    // ---- scatter output (reverse shift via gof); duplicate rows same bits ----
#pragma unroll
    for (int half = 0; half < 2; ++half) {
        int i = m0 + g + half*8;
        float inv = inv_l[half];
        float* dst = g_O + gof[i] + hc;
#pragma unroll
        for (int nt = 0; nt < 4; ++nt) {
            float2 v;
            v.x = o[nt][half*2+0] * inv;
            v.y = o[nt][half*2+1] * inv;
            *reinterpret_cast<float2*>(dst + nt*8 + 2*t) = v;
        }
    }
}

// ---------------------------------------------------------------------------
// Kernel C: output projection GEMM (unchanged, TF32 MMA).
// ---------------------------------------------------------------------------
__global__ __launch_bounds__(256) void proj_kernel(const float* __restrict__ Wp,
                                                   const float* __restrict__ bp,
                                                   float* __restrict__ out) {
    __shared__ unsigned As[32][136];
    __shared__ unsigned Bs[32][136];

    int bm = blockIdx.x;
    int bn = blockIdx.y;
    int tid = threadIdx.x;
    int warp = tid >> 5, lane = tid & 31;
    int g = lane >> 2, t = lane & 3;

    int wm = (warp & 1) * 64;
    int wn = (warp >> 1) * 32;

    float acc[4][4][4];
#pragma unroll
    for (int mi = 0; mi < 4; ++mi)
#pragma unroll
        for (int ni = 0; ni < 4; ++ni)
#pragma unroll
            for (int rr = 0; rr < 4; ++rr) acc[mi][ni][rr] = 0.f;

    const float* Ag = g_O + (size_t)bm * 128 * EMB;
    int ar = tid >> 1, ac = (tid & 1) * 16;
    int br = tid >> 3, bc = (tid & 7) * 16;

    for (int kb = 0; kb < EMB; kb += 32) {
#pragma unroll
        for (int i = 0; i < 4; ++i) {
            float4 v = *reinterpret_cast<const float4*>(Ag + (size_t)ar*EMB + kb + ac + i*4);
            As[ac + i*4 + 0][ar] = f2tf32(v.x);
            As[ac + i*4 + 1][ar] = f2tf32(v.y);
            As[ac + i*4 + 2][ar] = f2tf32(v.z);
            As[ac + i*4 + 3][ar] = f2tf32(v.w);
        }
#pragma unroll
        for (int i = 0; i < 4; ++i) {
            float4 v = *reinterpret_cast<const float4*>(Wp + (size_t)(kb + br)*EMB + bn*128 + bc + i*4);
            uint4 u;
            u.x = f2tf32(v.x); u.y = f2tf32(v.y);
            u.z = f2tf32(v.z); u.w = f2tf32(v.w);
            *reinterpret_cast<uint4*>(&Bs[br][bc + i*4]) = u;
        }
        __syncthreads();

#pragma unroll
        for (int ks = 0; ks < 4; ++ks) {
            int k0 = ks * 8;
            unsigned af[4][4];
#pragma unroll
            for (int mi = 0; mi < 4; ++mi) {
                int m0 = wm + mi*16;
                af[mi][0] = As[k0 + t    ][m0 + g    ];
                af[mi][1] = As[k0 + t    ][m0 + g + 8];
                af[mi][2] = As[k0 + t + 4][m0 + g    ];
                af[mi][3] = As[k0 + t + 4][m0 + g + 8];
            }
            unsigned bf[4][2];
#pragma unroll
            for (int ni = 0; ni < 4; ++ni) {
                int n0 = wn + ni*8;
                bf[ni][0] = Bs[k0 + t    ][n0 + g];
                bf[ni][1] = Bs[k0 + t + 4][n0 + g];
            }
#pragma unroll
            for (int mi = 0; mi < 4; ++mi)
#pragma unroll
                for (int ni = 0; ni < 4; ++ni)
                    mma_tf32(acc[mi][ni], af[mi][0], af[mi][1], af[mi][2], af[mi][3],
                             bf[ni][0], bf[ni][1]);
        }
        __syncthreads();
    }

#pragma unroll
    for (int ni = 0; ni < 4; ++ni) {
        int n = bn*128 + wn + ni*8 + 2*t;
        float2 bb = *reinterpret_cast<const float2*>(bp + n);
#pragma unroll
        for (int mi = 0; mi < 4; ++mi) {
            size_t m = (size_t)bm*128 + wm + mi*16;
            float2 v0, v1;
            v0.x = acc[mi][ni][0] + bb.x; v0.y = acc[mi][ni][1] + bb.y;
            v1.x = acc[mi][ni][2] + bb.x; v1.y = acc[mi][ni][3] + bb.y;
            *reinterpret_cast<float2*>(out + (m + g    )*EMB + n) = v0;
            *reinterpret_cast<float2*>(out + (m + g + 8)*EMB + n) = v1;
        }
    }
}

// ---------------------------------------------------------------------------
extern "C" void kernel_launch(void* const* d_in, const int* in_sizes, int n_in,
                              void* d_out, int out_size) {
    const float* x      = (const float*)d_in[0];
    const float* qkv_w  = (const float*)d_in[1];
    const float* qkv_b  = (const float*)d_in[2];
    const float* proj_w = (const float*)d_in[3];
    const float* proj_b = (const float*)d_in[4];
    const float* rpb    = (const float*)d_in[5];
    float* out = (float*)d_out;

    const int fused_smem = SMEM_FLOATS * 4;    // 62,856 B
    cudaFuncSetAttribute(fused_kernel, cudaFuncAttributeMaxDynamicSharedMemorySize, fused_smem);

    bias_kernel<<<(NHEAD*WD*WD + 511)/512, 512>>>(rpb);
    fused_kernel<<<BNUM*NWIN*4, 256, fused_smem>>>(x, qkv_w, qkv_b);
    dim3 grid(BNUM*NTOK/128, EMB/128);
    proj_kernel<<<grid, 256>>>(proj_w, proj_b, out);
}

// round 11
// speedup vs baseline: 1.1130x; 1.1130x over previous
#include <cuda_runtime.h>

// ---------------------------------------------------------------------------
// SWMSA: shifted-window multi-head self-attention (Swin block attention)
// B=32, H=W=56, WS=7, SS=3, NH=8, E=256, HD=32, NW=64, WD=49
// Kernel A: one-shot rel-pos-bias expansion, pre-combined with the shift mask
//           for the 4 distinct window types -> g_BiM[4][8][49][49]
// Kernel B: tensor-core fused QKV + attention; block = (window, 2 heads),
//           4 warps/head, 43.6KB smem, <=85 regs -> 3 blocks/SM
// Kernel C: output projection GEMM [TF32 MMA]
// ---------------------------------------------------------------------------

#define BNUM 32
#define HW   56
#define NHEAD 8
#define EMB  256
#define HDIM 32
#define NWIN 64
#define WD   49
#define NTOK (HW*HW)              // 3136

__device__ __align__(16) float g_O  [(size_t)BNUM*NTOK*EMB];
__device__ __align__(16) float g_BiM[4*NHEAD*WD*WD];   // 76832 floats (307KB, L2)

// ---------------------------------------------------------------------------
// Kernel A: bias + mask tables.
// Window type ty = Rw*2 + Cw, Rw = (wr==7), Cw = (wc==7).
// Region id of token (tr,tc): zr = Rw ? (tr<4?1:2) : 0 ; zc likewise.
// ---------------------------------------------------------------------------
__global__ __launch_bounds__(512) void bias_kernel(const float* __restrict__ rpb) {
    int i = blockIdx.x * 512 + threadIdx.x;
    if (i >= NHEAD*WD*WD) return;
    int h  = i / (WD*WD);
    int r2 = i - h*(WD*WD);
    int a  = r2 / WD;
    int bb = r2 - a*WD;
    int atr = a/7,  atc = a - 7*atr;
    int btr = bb/7, btc = bb - 7*btr;
    float bias = rpb[((atr - btr + 6)*13 + (atc - btc + 6))*NHEAD + h];
#pragma unroll
    for (int ty = 0; ty < 4; ++ty) {
        int Rw = ty >> 1, Cw = ty & 1;
        int ra = (Rw ? (atr<4?1:2) : 0)*3 + (Cw ? (atc<4?1:2) : 0);
        int rb = (Rw ? (btr<4?1:2) : 0)*3 + (Cw ? (btc<4?1:2) : 0);
        g_BiM[ty*(NHEAD*WD*WD) + i] = bias + ((ra == rb) ? 0.f : -100.f);
    }
}

// ---------------------------------------------------------------------------
__device__ __forceinline__ unsigned f2tf32(float f) {
    unsigned r;
    asm("cvt.rna.tf32.f32 %0, %1;" : "=r"(r) : "f"(f));
    return r;
}

__device__ __forceinline__ void mma_tf32(float* c, unsigned a0, unsigned a1,
                                         unsigned a2, unsigned a3,
                                         unsigned b0, unsigned b1) {
    asm volatile(
        "mma.sync.aligned.m16n8k8.row.col.f32.tf32.tf32.f32 "
        "{%0,%1,%2,%3}, {%4,%5,%6,%7}, {%8,%9}, {%0,%1,%2,%3};\n"
        : "+f"(c[0]), "+f"(c[1]), "+f"(c[2]), "+f"(c[3])
        : "r"(a0), "r"(a1), "r"(a2), "r"(a3), "r"(b0), "r"(b1));
}

// ---------------------------------------------------------------------------
// Fused kernel smem layout (floats), block = (window, 2 heads):
//   Ks  @ 0     : 2 heads x 32 d x 56 j (tf32)            = 3584
//   Vs  @ 3584  : 2 heads x 32 d x 60 j (tf32, zeroed)    = 3840
//   Ws  @ 7424  : 32 k x stride 104 (tf32)                = 3328
//   bs  @ 10752 : 96 (fp32)
//   gof @ 10848 : 64 ints (token -> global element offset)
//   total 10912 floats = 43,648 B -> 3 blocks/SM (256 thr, <=85 regs)
// ---------------------------------------------------------------------------
#define OFF_KS 0
#define KS_H   1792      // 32*56
#define OFF_VS 3584
#define VS_H   1920      // 32*60
#define OFF_WS 7424
#define WS_S   104
#define OFF_BS 10752
#define OFF_GO 10848
#define SMEM_FLOATS 10912

__global__ __launch_bounds__(256, 3) void fused_kernel(const float* __restrict__ x,
                                                       const float* __restrict__ Wq,
                                                       const float* __restrict__ bq) {
    extern __shared__ float sm[];
    float* bs  = sm + OFF_BS;
    int*   gof = reinterpret_cast<int*>(sm + OFF_GO);
    unsigned* Wsu = reinterpret_cast<unsigned*>(sm + OFF_WS);

    int bid = blockIdx.x;
    int hg = bid & 3, bw = bid >> 2;
    int b  = bw >> 6, w = bw & 63;
    int wr = w >> 3,  wc = w & 7;
    int tid = threadIdx.x, warp = tid >> 5, lane = tid & 31;
    int g = lane >> 2, t = lane & 3;
    int lh = warp >> 2, p = warp & 3;          // local head (0/1), warp-in-head
    int h = hg*2 + lh;
    int m0 = p*16 - (p == 3 ? 15 : 0);         // m-tile base: 0,16,32,33

    // zero Vs (j-pad columns must be exact 0 for PV)
    {
        float4* z = reinterpret_cast<float4*>(sm + OFF_VS);
        for (int i = tid; i < 3840/4; i += 256) z[i] = make_float4(0,0,0,0);
    }
    // stage qkv weights (tf32) + bias (fp32)
    for (int i = tid; i < 32*96; i += 256) {
        int k = i / 96, n = i - k*96;
        Wsu[k*WS_S + n] = f2tf32(Wq[i]);
    }
    if (tid < 96) bs[tid] = bq[tid];
    if (tid < WD) {
        int tr = tid/7, tc = tid - 7*tr;
        int row = wr*7 + tr + 3; if (row >= HW) row -= HW;
        int col = wc*7 + tc + 3; if (col >= HW) col -= HW;
        gof[tid] = (b*NTOK + row*HW + col)*EMB;
    }
    __syncthreads();

    // ---- A-frags (x rows, this head's 32-col slice) direct from global ----
    int hc = h*HDIM;
    int r0 = gof[m0+g]   + hc;
    int r1 = gof[m0+g+8] + hc;
    unsigned a_[4][4];
#pragma unroll
    for (int ks = 0; ks < 4; ++ks) {
        int k0 = ks*8;
        a_[ks][0] = f2tf32(__ldg(x + r0 + k0 + t    ));
        a_[ks][1] = f2tf32(__ldg(x + r1 + k0 + t    ));
        a_[ks][2] = f2tf32(__ldg(x + r0 + k0 + t + 4));
        a_[ks][3] = f2tf32(__ldg(x + r1 + k0 + t + 4));
    }

    // ---- Q pass (cols 0..31) -> c-frags (scaled, tf32) ----
    unsigned qu[4][4];
    const float qscale = 0.17677669529663687f;
#pragma unroll
    for (int nt = 0; nt < 4; ++nt) {
        float c4[4] = {0.f,0.f,0.f,0.f};
#pragma unroll
        for (int ks = 0; ks < 4; ++ks) {
            int k0 = ks*8;
            unsigned b0 = Wsu[(k0+t  )*WS_S + nt*8 + g];
            unsigned b1 = Wsu[(k0+t+4)*WS_S + nt*8 + g];
            mma_tf32(c4, a_[ks][0],a_[ks][1],a_[ks][2],a_[ks][3], b0,b1);
        }
        int d0 = nt*8 + 2*t;
        qu[nt][0] = f2tf32((c4[0] + bs[d0  ]) * qscale);
        qu[nt][1] = f2tf32((c4[1] + bs[d0+1]) * qscale);
        qu[nt][2] = f2tf32((c4[2] + bs[d0  ]) * qscale);
        qu[nt][3] = f2tf32((c4[3] + bs[d0+1]) * qscale);
    }
    // ---- K pass (cols 32..63) -> Ks[d][j] stride 56 ----
    {
        unsigned* Kh = reinterpret_cast<unsigned*>(sm + OFF_KS) + lh*KS_H;
#pragma unroll
        for (int nt = 0; nt < 4; ++nt) {
            float c4[4] = {0.f,0.f,0.f,0.f};
#pragma unroll
            for (int ks = 0; ks < 4; ++ks) {
                int k0 = ks*8;
                unsigned b0 = Wsu[(k0+t  )*WS_S + 32 + nt*8 + g];
                unsigned b1 = Wsu[(k0+t+4)*WS_S + 32 + nt*8 + g];
                mma_tf32(c4, a_[ks][0],a_[ks][1],a_[ks][2],a_[ks][3], b0,b1);
            }
            int d0 = nt*8 + 2*t;
            Kh[(d0  )*56 + m0+g  ] = f2tf32(c4[0] + bs[32+d0  ]);
            Kh[(d0+1)*56 + m0+g  ] = f2tf32(c4[1] + bs[32+d0+1]);
            Kh[(d0  )*56 + m0+g+8] = f2tf32(c4[2] + bs[32+d0  ]);
            Kh[(d0+1)*56 + m0+g+8] = f2tf32(c4[3] + bs[32+d0+1]);
        }
    }
    // ---- V pass (cols 64..95) -> Vs[d][j] stride 60 (transposed) ----
    {
        unsigned* Vh = reinterpret_cast<unsigned*>(sm + OFF_VS) + lh*VS_H;
#pragma unroll
        for (int nt = 0; nt < 4; ++nt) {
            float c4[4] = {0.f,0.f,0.f,0.f};
#pragma unroll
            for (int ks = 0; ks < 4; ++ks) {
                int k0 = ks*8;
                unsigned b0 = Wsu[(k0+t  )*WS_S + 64 + nt*8 + g];
                unsigned b1 = Wsu[(k0+t+4)*WS_S + 64 + nt*8 + g];
                mma_tf32(c4, a_[ks][0],a_[ks][1],a_[ks][2],a_[ks][3], b0,b1);
            }
            int d0 = nt*8 + 2*t;
            Vh[(d0  )*60 + m0+g  ] = f2tf32(c4[0] + bs[64+d0  ]);
            Vh[(d0+1)*60 + m0+g  ] = f2tf32(c4[1] + bs[64+d0+1]);
            Vh[(d0  )*60 + m0+g+8] = f2tf32(c4[2] + bs[64+d0  ]);
            Vh[(d0+1)*60 + m0+g+8] = f2tf32(c4[3] + bs[64+d0+1]);
        }
    }

    // rearrange Q c-frags -> a-frags via warp shuffles (warp-local, pre-sync ok)
    int src0 = (g << 2) | (t >> 1);
    unsigned qa[4][4];
#pragma unroll
    for (int ks = 0; ks < 4; ++ks) {
        unsigned v00 = __shfl_sync(0xffffffffu, qu[ks][0], src0);
        unsigned v01 = __shfl_sync(0xffffffffu, qu[ks][1], src0);
        unsigned v02 = __shfl_sync(0xffffffffu, qu[ks][2], src0);
        unsigned v03 = __shfl_sync(0xffffffffu, qu[ks][3], src0);
        unsigned v10 = __shfl_sync(0xffffffffu, qu[ks][0], src0+2);
        unsigned v11 = __shfl_sync(0xffffffffu, qu[ks][1], src0+2);
        unsigned v12 = __shfl_sync(0xffffffffu, qu[ks][2], src0+2);
        unsigned v13 = __shfl_sync(0xffffffffu, qu[ks][3], src0+2);
        bool odd = (t & 1);
        qa[ks][0] = odd ? v01 : v00;
        qa[ks][1] = odd ? v03 : v02;
        qa[ks][2] = odd ? v11 : v10;
        qa[ks][3] = odd ? v13 : v12;
    }

    __syncthreads();   // K/V from all 4 warps of each head visible

    // ---- scores: S = Q · K^T ----
    float s[7][4];
#pragma unroll
    for (int nt = 0; nt < 7; ++nt)
        s[nt][0]=s[nt][1]=s[nt][2]=s[nt][3]=0.f;
    {
        const unsigned* Kh = reinterpret_cast<const unsigned*>(sm + OFF_KS) + lh*KS_H;
#pragma unroll
        for (int ks = 0; ks < 4; ++ks) {
            int k0 = ks*8;
#pragma unroll
            for (int nt = 0; nt < 7; ++nt) {
                unsigned b0 = Kh[(k0+t  )*56 + nt*8 + g];
                unsigned b1 = Kh[(k0+t+4)*56 + nt*8 + g];
                mma_tf32(s[nt], qa[ks][0],qa[ks][1],qa[ks][2],qa[ks][3], b0,b1);
            }
        }
    }

    // ---- softmax (single pass; bias+mask from per-type table, L2) ----
    int ty = ((wr == 7) ? 2 : 0) + ((wc == 7) ? 1 : 0);
    const float* Bh = g_BiM + (ty*NHEAD + h)*(WD*WD);
    float inv_l[2];
#pragma unroll
    for (int half = 0; half < 2; ++half) {
        int i = m0 + g + half*8;
        const float* Br = Bh + i*WD;
        float mx = -1e30f;
#pragma unroll
        for (int nt = 0; nt < 7; ++nt) {
#pragma unroll
            for (int c = 0; c < 2; ++c) {
                int j = nt*8 + 2*t + c;
                float v = (j < WD) ? s[nt][half*2+c] + __ldg(Br + j) : -1e30f;
                s[nt][half*2+c] = v;
                mx = fmaxf(mx, v);
            }
        }
        mx = fmaxf(mx, __shfl_xor_sync(0xffffffffu, mx, 1));
        mx = fmaxf(mx, __shfl_xor_sync(0xffffffffu, mx, 2));
        float l = 0.f;
#pragma unroll
        for (int nt = 0; nt < 7; ++nt)
#pragma unroll
            for (int c = 0; c < 2; ++c) {
                float e = __expf(s[nt][half*2+c] - mx);
                s[nt][half*2+c] = e;
                l += e;
            }
        l += __shfl_xor_sync(0xffffffffu, l, 1);
        l += __shfl_xor_sync(0xffffffffu, l, 2);
        inv_l[half] = 1.f / l;
    }
    // convert P to tf32 bits in place
#pragma unroll
    for (int nt = 0; nt < 7; ++nt)
#pragma unroll
        for (int c = 0; c < 4; ++c)
            s[nt][c] = __uint_as_float(f2tf32(s[nt][c]));

    // ---- PV: O = P · V  (V stored [d][j]: B[k=j][n=d] = Vh[n*60 + k]) ----
    float o[4][4];
#pragma unroll
    for (int nt = 0; nt < 4; ++nt)
        o[nt][0]=o[nt][1]=o[nt][2]=o[nt][3]=0.f;
    {
        const unsigned* Vh = reinterpret_cast<const unsigned*>(sm + OFF_VS) + lh*VS_H;
#pragma unroll
        for (int ks = 0; ks < 7; ++ks) {
            int k0 = ks*8;
            float v00 = __shfl_sync(0xffffffffu, s[ks][0], src0);
            float v01 = __shfl_sync(0xffffffffu, s[ks][1], src0);
            float v02 = __shfl_sync(0xffffffffu, s[ks][2], src0);
            float v03 = __shfl_sync(0xffffffffu, s[ks][3], src0);
            float v10 = __shfl_sync(0xffffffffu, s[ks][0], src0+2);
            float v11 = __shfl_sync(0xffffffffu, s[ks][1], src0+2);
            float v12 = __shfl_sync(0xffffffffu, s[ks][2], src0+2);
            float v13 = __shfl_sync(0xffffffffu, s[ks][3], src0+2);
            bool odd = (t & 1);
            unsigned pa0 = __float_as_uint(odd ? v01 : v00);
            unsigned pa1 = __float_as_uint(odd ? v03 : v02);
            unsigned pa2 = __float_as_uint(odd ? v11 : v10);
            unsigned pa3 = __float_as_uint(odd ? v13 : v12);
#pragma unroll
            for (int nt = 0; nt < 4; ++nt) {
                unsigned b0 = Vh[(nt*8+g)*60 + k0+t  ];
                unsigned b1 = Vh[(nt*8+g)*60 + k0+t+4];
                mma_tf32(o[nt], pa0,pa1,pa2,pa3, b0,b1);
            }
        }
    }

    // ---- scatter output (reverse shift via gof); duplicate rows same bits ----
#pragma unroll
    for (int half = 0; half < 2; ++half) {
        int i = m0 + g + half*8;
        float inv = inv_l[half];
        float* dst = g_O + gof[i] + hc;
#pragma unroll
        for (int nt = 0; nt < 4; ++nt) {
            float2 v;
            v.x = o[nt][half*2+0] * inv;
            v.y = o[nt][half*2+1] * inv;
            *reinterpret_cast<float2*>(dst + nt*8 + 2*t) = v;
        }
    }
}

// ---------------------------------------------------------------------------
// Kernel C: output projection GEMM (unchanged, TF32 MMA).
// ---------------------------------------------------------------------------
__global__ __launch_bounds__(256) void proj_kernel(const float* __restrict__ Wp,
                                                   const float* __restrict__ bp,
                                                   float* __restrict__ out) {
    __shared__ unsigned As[32][136];
    __shared__ unsigned Bs[32][136];

    int bm = blockIdx.x;
    int bn = blockIdx.y;
    int tid = threadIdx.x;
    int warp = tid >> 5, lane = tid & 31;
    int g = lane >> 2, t = lane & 3;

    int wm = (warp & 1) * 64;
    int wn = (warp >> 1) * 32;

    float acc[4][4][4];
#pragma unroll
    for (int mi = 0; mi < 4; ++mi)
#pragma unroll
        for (int ni = 0; ni < 4; ++ni)
#pragma unroll
            for (int rr = 0; rr < 4; ++rr) acc[mi][ni][rr] = 0.f;

    const float* Ag = g_O + (size_t)bm * 128 * EMB;
    int ar = tid >> 1, ac = (tid & 1) * 16;
    int br = tid >> 3, bc = (tid & 7) * 16;

    for (int kb = 0; kb < EMB; kb += 32) {
#pragma unroll
        for (int i = 0; i < 4; ++i) {
            float4 v = *reinterpret_cast<const float4*>(Ag + (size_t)ar*EMB + kb + ac + i*4);
            As[ac + i*4 + 0][ar] = f2tf32(v.x);
            As[ac + i*4 + 1][ar] = f2tf32(v.y);
            As[ac + i*4 + 2][ar] = f2tf32(v.z);
            As[ac + i*4 + 3][ar] = f2tf32(v.w);
        }
#pragma unroll
        for (int i = 0; i < 4; ++i) {
            float4 v = *reinterpret_cast<const float4*>(Wp + (size_t)(kb + br)*EMB + bn*128 + bc + i*4);
            uint4 u;
            u.x = f2tf32(v.x); u.y = f2tf32(v.y);
            u.z = f2tf32(v.z); u.w = f2tf32(v.w);
            *reinterpret_cast<uint4*>(&Bs[br][bc + i*4]) = u;
        }
        __syncthreads();

#pragma unroll
        for (int ks = 0; ks < 4; ++ks) {
            int k0 = ks * 8;
            unsigned af[4][4];
#pragma unroll
            for (int mi = 0; mi < 4; ++mi) {
                int m0 = wm + mi*16;
                af[mi][0] = As[k0 + t    ][m0 + g    ];
                af[mi][1] = As[k0 + t    ][m0 + g + 8];
                af[mi][2] = As[k0 + t + 4][m0 + g    ];
                af[mi][3] = As[k0 + t + 4][m0 + g + 8];
            }
            unsigned bf[4][2];
#pragma unroll
            for (int ni = 0; ni < 4; ++ni) {
                int n0 = wn + ni*8;
                bf[ni][0] = Bs[k0 + t    ][n0 + g];
                bf[ni][1] = Bs[k0 + t + 4][n0 + g];
            }
#pragma unroll
            for (int mi = 0; mi < 4; ++mi)
#pragma unroll
                for (int ni = 0; ni < 4; ++ni)
                    mma_tf32(acc[mi][ni], af[mi][0], af[mi][1], af[mi][2], af[mi][3],
                             bf[ni][0], bf[ni][1]);
        }
        __syncthreads();
    }

#pragma unroll
    for (int ni = 0; ni < 4; ++ni) {
        int n = bn*128 + wn + ni*8 + 2*t;
        float2 bb = *reinterpret_cast<const float2*>(bp + n);
#pragma unroll
        for (int mi = 0; mi < 4; ++mi) {
            size_t m = (size_t)bm*128 + wm + mi*16;
            float2 v0, v1;
            v0.x = acc[mi][ni][0] + bb.x; v0.y = acc[mi][ni][1] + bb.y;
            v1.x = acc[mi][ni][2] + bb.x; v1.y = acc[mi][ni][3] + bb.y;
            *reinterpret_cast<float2*>(out + (m + g    )*EMB + n) = v0;
            *reinterpret_cast<float2*>(out + (m + g + 8)*EMB + n) = v1;
        }
    }
}

// ---------------------------------------------------------------------------
extern "C" void kernel_launch(void* const* d_in, const int* in_sizes, int n_in,
                              void* d_out, int out_size) {
    const float* x      = (const float*)d_in[0];
    const float* qkv_w  = (const float*)d_in[1];
    const float* qkv_b  = (const float*)d_in[2];
    const float* proj_w = (const float*)d_in[3];
    const float* proj_b = (const float*)d_in[4];
    const float* rpb    = (const float*)d_in[5];
    float* out = (float*)d_out;

    const int fused_smem = SMEM_FLOATS * 4;    // 43,648 B
    cudaFuncSetAttribute(fused_kernel, cudaFuncAttributeMaxDynamicSharedMemorySize, fused_smem);

    bias_kernel<<<(NHEAD*WD*WD + 511)/512, 512>>>(rpb);
    fused_kernel<<<BNUM*NWIN*4, 256, fused_smem>>>(x, qkv_w, qkv_b);
    dim3 grid(BNUM*NTOK/128, EMB/128);
    proj_kernel<<<grid, 256>>>(proj_w, proj_b, out);
}